// round 7
// baseline (speedup 1.0000x reference)
#include <cuda_runtime.h>
#include <math.h>

#define NSLOPE 0.2f
#define NN 1024
#define F 128
#define NBLK 256
#define NTHR 256

__device__ float g_XT[NN * F];   // feature-major activations [f][n]
__device__ float g_HT[NN * F];   // feature-major conv features [f][n]
__device__ float g_H[NN * F];    // row-major (final conv)
__device__ float g_asf[NN];
__device__ float g_adf[NN];
__device__ unsigned g_bar;

__device__ __forceinline__ float lrelu(float x) { return x > 0.f ? x : NSLOPE * x; }

// order-preserving float->uint encode
__device__ __forceinline__ unsigned fenc(float f) {
    unsigned u = __float_as_uint(f);
    return (u & 0x80000000u) ? ~u : (u | 0x80000000u);
}

// ---------------------------------------------------------------------------
struct SmemGemm {
    float Wt[64 * 129];
    float xs[8][128];
};
struct SmemAttn {
    unsigned sU[512];
    float sK0[512];
    float sV0[512];
    float4 sSP[513];
    float2 wt1[8], wt2[8];
};
struct SmemFinal {
    float sAsf[512];
    float4 swq[512][2];
    float sAdf[8], sM[8], sSelf[8], sDen[8];
    float pr[8][128];
    float dred[8][256];
    float red[8];
};
union SmemAll {
    SmemGemm g;
    SmemAttn a;
    SmemFinal f;
};

// ---------------------------------------------------------------------------
// software grid barrier: arrive (atomic) + spin (volatile); threadfence both
// sides (gpu scope -> CCTL.IVALL, no stale L1 across phases)
__device__ __forceinline__ void gsync(unsigned target) {
    __syncthreads();
    if (threadIdx.x == 0) {
        __threadfence();
        atomicAdd(&g_bar, 1u);
        while (*(volatile unsigned*)&g_bar < target) {}
    }
    __syncthreads();
    __threadfence();
}

// ---------------------------------------------------------------------------
// GEMM phase: 256 virtual blocks = (row-block 0..127) x (col-half), 256 thr.
// 8 rows x 64 cols/block, 2 rows/thread. W transposed in smem (pad 129).
// MODE 0: desc1|desc2 -> HT; MODE 1: XT -> HT; MODE 2: XT -> H (row-major).
template <int MODE>
__device__ void gemm_phase(int bid, const float* __restrict__ XT,
                           const float* __restrict__ d1, const float* __restrict__ d2,
                           const float* __restrict__ W, float* __restrict__ OUT,
                           SmemGemm& S) {
    int tid = threadIdx.x;
    int cs = (bid & 1) * 64;
    int n0 = (bid >> 1) * 8;
    int c = tid & 63;
    int rr = tid >> 6;  // 0..3

#pragma unroll
    for (int i = 0; i < 8; i++) {
        int f = tid + i * 256;
        int k = f >> 4, cq = f & 15;
        float4 w4 = *reinterpret_cast<const float4*>(W + k * F + cs + cq * 4);
        S.Wt[(cq * 4 + 0) * 129 + k] = w4.x;
        S.Wt[(cq * 4 + 1) * 129 + k] = w4.y;
        S.Wt[(cq * 4 + 2) * 129 + k] = w4.z;
        S.Wt[(cq * 4 + 3) * 129 + k] = w4.w;
    }
    if (MODE == 0) {
        int r = tid >> 5, cq = tid & 31;
        int n = n0 + r;
        float4 x4 = (n < 512) ? reinterpret_cast<const float4*>(d1)[n * 32 + cq]
                              : reinterpret_cast<const float4*>(d2)[(n - 512) * 32 + cq];
        *reinterpret_cast<float4*>(&S.xs[r][cq * 4]) = x4;
    } else {
        const float4* XT4 = reinterpret_cast<const float4*>(XT);
        int k = tid >> 1, q = tid & 1;
        float4 x4 = XT4[k * 256 + (n0 >> 2) + q];
        S.xs[q * 4 + 0][k] = x4.x;
        S.xs[q * 4 + 1][k] = x4.y;
        S.xs[q * 4 + 2][k] = x4.z;
        S.xs[q * 4 + 3][k] = x4.w;
    }
    __syncthreads();

    float a0 = 0.f, a1 = 0.f;
#pragma unroll 4
    for (int kq = 0; kq < 32; kq++) {
        float w0 = S.Wt[c * 129 + kq * 4 + 0];
        float w1 = S.Wt[c * 129 + kq * 4 + 1];
        float w2 = S.Wt[c * 129 + kq * 4 + 2];
        float w3 = S.Wt[c * 129 + kq * 4 + 3];
        float4 x0 = *reinterpret_cast<const float4*>(&S.xs[rr * 2 + 0][kq * 4]);
        float4 x1 = *reinterpret_cast<const float4*>(&S.xs[rr * 2 + 1][kq * 4]);
        a0 = fmaf(x0.x, w0, fmaf(x0.y, w1, fmaf(x0.z, w2, fmaf(x0.w, w3, a0))));
        a1 = fmaf(x1.x, w0, fmaf(x1.y, w1, fmaf(x1.z, w2, fmaf(x1.w, w3, a1))));
    }
    if (MODE == 2) {
        OUT[(n0 + rr * 2 + 0) * F + cs + c] = a0;
        OUT[(n0 + rr * 2 + 1) * F + cs + c] = a1;
    } else {
        *reinterpret_cast<float2*>(OUT + (cs + c) * NN + n0 + rr * 2) = make_float2(a0, a1);
    }
}

// ---------------------------------------------------------------------------
__device__ __forceinline__ float2 warp_incl_scan2(float2 v, int lane) {
#pragma unroll
    for (int d = 1; d < 32; d <<= 1) {
        float x = __shfl_up_sync(0xffffffffu, v.x, d);
        float y = __shfl_up_sync(0xffffffffu, v.y, d);
        if (lane >= d) { v.x += x; v.y += y; }
    }
    return v;
}
__device__ __forceinline__ float2 warp_incl_sufscan2(float2 v, int lane) {
#pragma unroll
    for (int d = 1; d < 32; d <<= 1) {
        float x = __shfl_down_sync(0xffffffffu, v.x, d);
        float y = __shfl_down_sync(0xffffffffu, v.y, d);
        if (lane + d < 32) { v.x += x; v.y += y; }
    }
    return v;
}

// ---------------------------------------------------------------------------
// Attention phase: virtual block = (head, dst group): h = bid>>1, dg = bid&1.
// Packed-key bitonic sort (encoded key | 9-bit index) -> 1 shfl per exchange;
// exact keys/values regathered by index for the branch-sum scans.
template <bool CROSS>
__device__ void attn_phase(int bid, const float* __restrict__ HT,
                           const float* __restrict__ a_src, const float* __restrict__ a_dst,
                           const float* __restrict__ bias, float* __restrict__ XTo,
                           SmemAttn& S) {
    int t = threadIdx.x;  // 0..255
    int lane = t & 31;
    int w = t >> 5;
    int h = bid >> 1;
    int dg = bid & 1;
    int sg = CROSS ? (1 - dg) : dg;

    float asrc = a_src[h], adst = a_dst[h], bh = bias[h];

    unsigned u[2];
    float Hd[2];
    {
        float2 v2 = *reinterpret_cast<const float2*>(HT + h * NN + sg * 512 + t * 2);
        float2 h2 = *reinterpret_cast<const float2*>(HT + h * NN + dg * 512 + t * 2);
        Hd[0] = h2.x; Hd[1] = h2.y;
        float k0 = v2.x * asrc, k1 = v2.y * asrc;
        S.sK0[t * 2 + 0] = k0; S.sV0[t * 2 + 0] = v2.x;
        S.sK0[t * 2 + 1] = k1; S.sV0[t * 2 + 1] = v2.y;
        u[0] = (fenc(k0) & ~511u) | (unsigned)(t * 2 + 0);
        u[1] = (fenc(k1) & ~511u) | (unsigned)(t * 2 + 1);
    }
    __syncthreads();

    // bitonic sort ascending on packed keys; element i = t*2+e
    for (int K2 = 2; K2 <= 512; K2 <<= 1) {
        for (int J = K2 >> 1; J >= 2; J >>= 1) {
            bool up = (((t * 2) & K2) == 0);
            if (J >= 64) {
                __syncthreads();
                S.sU[t * 2] = u[0];
                S.sU[t * 2 + 1] = u[1];
                __syncthreads();
                int d = J >> 1;
                bool low = ((t & d) == 0);
                bool want_small = (low == up);
#pragma unroll
                for (int e = 0; e < 2; e++) {
                    unsigned uo = S.sU[(t * 2 + e) ^ J];
                    bool take = want_small ? (uo < u[e]) : (uo > u[e]);
                    if (take) u[e] = uo;
                }
            } else {
                int d = J >> 1;  // lane distance 1..16
                bool low = ((t & d) == 0);
                bool want_small = (low == up);
#pragma unroll
                for (int e = 0; e < 2; e++) {
                    unsigned uo = __shfl_xor_sync(0xffffffffu, u[e], d);
                    bool take = want_small ? (uo < u[e]) : (uo > u[e]);
                    if (take) u[e] = uo;
                }
            }
        }
        {  // J == 1: intra-thread pair
            bool up = (((t * 2) & K2) == 0);
            if ((u[0] > u[1]) == up) { unsigned tmp = u[0]; u[0] = u[1]; u[1] = tmp; }
        }
    }

    __syncthreads();
    S.sU[t * 2] = u[0];
    S.sU[t * 2 + 1] = u[1];
    __syncthreads();
    float M = S.sK0[S.sU[511] & 511u];

    // regather exact key/value of this thread's 2 sorted elements
    float kx[2], vx[2];
#pragma unroll
    for (int e = 0; e < 2; e++) {
        unsigned idx = u[e] & 511u;
        kx[e] = S.sK0[idx];
        vx[e] = S.sV0[idx];
    }

    // local scans
    float2 tp1[2], lp2[2], lp1[2];
    float2 c2 = make_float2(0.f, 0.f);
#pragma unroll
    for (int e = 0; e < 2; e++) {
        float q1 = __expf(kx[e] - M);
        float q2 = __expf(NSLOPE * (kx[e] - M));
        tp1[e] = make_float2(q1, q1 * vx[e]);
        c2.x += q2; c2.y += q2 * vx[e];
        lp2[e] = c2;
    }
    float2 c1 = make_float2(0.f, 0.f);
#pragma unroll
    for (int e = 1; e >= 0; e--) {
        c1.x += tp1[e].x; c1.y += tp1[e].y;
        lp1[e] = c1;
    }

    float2 tincl = warp_incl_scan2(lp2[1], lane);
    float2 texcl;
    texcl.x = __shfl_up_sync(0xffffffffu, tincl.x, 1);
    texcl.y = __shfl_up_sync(0xffffffffu, tincl.y, 1);
    if (lane == 0) texcl = make_float2(0.f, 0.f);
    if (lane == 31) S.wt2[w] = tincl;

    float2 sincl = warp_incl_sufscan2(lp1[0], lane);
    float2 sexcl;
    sexcl.x = __shfl_down_sync(0xffffffffu, sincl.x, 1);
    sexcl.y = __shfl_down_sync(0xffffffffu, sincl.y, 1);
    if (lane == 31) sexcl = make_float2(0.f, 0.f);
    if (lane == 0) S.wt1[w] = sincl;
    __syncthreads();

    float2 base2 = texcl, base1 = sexcl;
#pragma unroll
    for (int ww = 0; ww < 8; ww++) {
        if (ww < w) { base2.x += S.wt2[ww].x; base2.y += S.wt2[ww].y; }
        if (ww > w) { base1.x += S.wt1[ww].x; base1.y += S.wt1[ww].y; }
    }
#pragma unroll
    for (int e = 0; e < 2; e++) {
        int j = t * 2 + e;
        float2 pre = base2;
        if (e > 0) { pre.x += lp2[0].x; pre.y += lp2[0].y; }
        S.sSP[j] = make_float4(base1.x + lp1[e].x, base1.y + lp1[e].y, pre.x, pre.y);
    }
    if (t == 255)
        S.sSP[512] = make_float4(0.f, 0.f, base2.x + lp2[1].x, base2.y + lp2[1].y);
    __syncthreads();

    // per-dst: binary search (encoded domain) + branch-sum combine
    float adv[2];
    unsigned ue[2];
    int pos[2];
#pragma unroll
    for (int e = 0; e < 2; e++) {
        adv[e] = Hd[e] * adst;
        ue[e] = fenc(-adv[e]);
        pos[e] = 0;
    }
#pragma unroll
    for (int half = 256; half >= 1; half >>= 1) {
#pragma unroll
        for (int e = 0; e < 2; e++)
            if (S.sU[pos[e] + half - 1] <= ue[e]) pos[e] += half;
    }
#pragma unroll
    for (int e = 0; e < 2; e++)
        if (S.sU[pos[e]] <= ue[e]) pos[e]++;

    float oval[2];
#pragma unroll
    for (int e = 0; e < 2; e++) {
        float4 Sv = S.sSP[pos[e]];
        float ad = adv[e];
        float T = M + ad;
        float tmax = T, ts = 0.f;
        if (CROSS) {
            ts = Hd[e] * asrc + ad;
            tmax = fmaxf(tmax, ts);
        }
        float C = lrelu(tmax);
        float f1 = __expf(T - C);
        float f2 = __expf(NSLOPE * T - C);
        float num = f1 * Sv.y + f2 * Sv.w;
        float den = f1 * Sv.x + f2 * Sv.z;
        if (CROSS) {
            float ws = __expf(lrelu(ts) - C);
            num = fmaf(ws, Hd[e], num);
            den += ws;
        }
        float o = num / (den + 1e-16f) + bh;
        oval[e] = o > 0.f ? o : expm1f(o);  // ELU
    }
    *reinterpret_cast<float2*>(XTo + h * NN + dg * 512 + t * 2) =
        make_float2(oval[0], oval[1]);
}

// ---------------------------------------------------------------------------
// dots phase: blocks 0..127, warp per node (8 nodes/block)
__device__ void dots_phase(int bid, const float* __restrict__ H,
                           const float* __restrict__ a_s, const float* __restrict__ a_d,
                           float* __restrict__ asf, float* __restrict__ adf) {
    if (bid >= 128) return;
    int w = threadIdx.x >> 5, lane = threadIdx.x & 31;
    int n = bid * 8 + w;
    float4 hv = reinterpret_cast<const float4*>(H + n * F)[lane];
    float4 s4 = reinterpret_cast<const float4*>(a_s)[lane];
    float4 d4 = reinterpret_cast<const float4*>(a_d)[lane];
    float s1 = hv.x * s4.x + hv.y * s4.y + hv.z * s4.z + hv.w * s4.w;
    float s2 = hv.x * d4.x + hv.y * d4.y + hv.z * d4.z + hv.w * d4.w;
#pragma unroll
    for (int o = 16; o; o >>= 1) {
        s1 += __shfl_xor_sync(0xffffffffu, s1, o);
        s2 += __shfl_xor_sync(0xffffffffu, s2, o);
    }
    if (lane == 0) { asf[n] = s1; adf[n] = s2; }
}

// ---------------------------------------------------------------------------
// final phase: blocks 0..127, 8 dsts/block, 256 threads (128 cols x 2 halves)
__device__ void final_phase(int bid, const float* __restrict__ H,
                            const float* __restrict__ asf, const float* __restrict__ adf,
                            const float* __restrict__ bias, float* __restrict__ out,
                            SmemFinal& S) {
    int d0 = bid * 8;
    int dg = d0 >> 9;
    int sg = 1 - dg;
    int tid = threadIdx.x;
    int col = tid & 127, sh = tid >> 7;
    int w = tid >> 5, lane = tid & 31;

    float mloc = -1e30f;
    for (int s = tid; s < 512; s += 256) {
        float v = asf[sg * 512 + s];
        S.sAsf[s] = v;
        mloc = fmaxf(mloc, v);
    }
#pragma unroll
    for (int o = 16; o; o >>= 1) mloc = fmaxf(mloc, __shfl_xor_sync(0xffffffffu, mloc, o));
    if (lane == 0) S.red[w] = mloc;
    __syncthreads();
    float maxasf = S.red[0];
#pragma unroll
    for (int ww = 1; ww < 8; ww++) maxasf = fmaxf(maxasf, S.red[ww]);

    if (tid < 8) {
        int dn = d0 + tid;
        float ad = adf[dn];
        float ts = asf[dn] + ad;
        float tmax = fmaxf(maxasf + ad, ts);
        float mm = lrelu(tmax);
        S.sAdf[tid] = ad;
        S.sM[tid] = mm;
        S.sSelf[tid] = __expf(lrelu(ts) - mm);
    }
    __syncthreads();

    float dl[8] = {0, 0, 0, 0, 0, 0, 0, 0};
    for (int s = tid; s < 512; s += 256) {
        float a = S.sAsf[s];
        float wv[8];
#pragma unroll
        for (int d = 0; d < 8; d++) {
            wv[d] = __expf(lrelu(a + S.sAdf[d]) - S.sM[d]);
            dl[d] += wv[d];
        }
        S.swq[s][0] = make_float4(wv[0], wv[1], wv[2], wv[3]);
        S.swq[s][1] = make_float4(wv[4], wv[5], wv[6], wv[7]);
    }
#pragma unroll
    for (int d = 0; d < 8; d++) S.dred[d][tid] = dl[d];
    __syncthreads();
    {
        float x = S.dred[w][lane] + S.dred[w][lane + 32] + S.dred[w][lane + 64] +
                  S.dred[w][lane + 96] + S.dred[w][lane + 128] + S.dred[w][lane + 160] +
                  S.dred[w][lane + 192] + S.dred[w][lane + 224];
#pragma unroll
        for (int o = 16; o; o >>= 1) x += __shfl_xor_sync(0xffffffffu, x, o);
        if (lane == 0) S.sDen[w] = x;
    }
    __syncthreads();

    float acc[8] = {0, 0, 0, 0, 0, 0, 0, 0};
    const float* Hs = H + (sg * 512 + sh * 256) * F + col;
#pragma unroll 2
    for (int s = 0; s < 256; s++) {
        float hv = Hs[s * F];
        int ss = sh * 256 + s;
        float4 w0 = S.swq[ss][0];
        float4 w1 = S.swq[ss][1];
        acc[0] = fmaf(w0.x, hv, acc[0]);
        acc[1] = fmaf(w0.y, hv, acc[1]);
        acc[2] = fmaf(w0.z, hv, acc[2]);
        acc[3] = fmaf(w0.w, hv, acc[3]);
        acc[4] = fmaf(w1.x, hv, acc[4]);
        acc[5] = fmaf(w1.y, hv, acc[5]);
        acc[6] = fmaf(w1.z, hv, acc[6]);
        acc[7] = fmaf(w1.w, hv, acc[7]);
    }
    if (sh) {
#pragma unroll
        for (int d = 0; d < 8; d++) S.pr[d][col] = acc[d];
    }
    __syncthreads();
    if (!sh) {
        float bc = bias[col];
#pragma unroll
        for (int d = 0; d < 8; d++) {
            int dn = d0 + d;
            float Hdv = H[dn * F + col];
            float num = acc[d] + S.pr[d][col] + S.sSelf[d] * Hdv;
            out[dn * F + col] = num / (S.sDen[d] + S.sSelf[d] + 1e-16f) + bc;
        }
    }
}

// ---------------------------------------------------------------------------
__global__ void reset_bar() { g_bar = 0; }

__global__ void __launch_bounds__(NTHR)
mega(const float* __restrict__ desc1, const float* __restrict__ desc2,
     const float* __restrict__ W1, const float* __restrict__ as1,
     const float* __restrict__ ad1, const float* __restrict__ b1,
     const float* __restrict__ W2, const float* __restrict__ as2,
     const float* __restrict__ ad2, const float* __restrict__ b2,
     float* __restrict__ out) {
    __shared__ SmemAll sm;
    int bid = blockIdx.x;

    gemm_phase<0>(bid, nullptr, desc1, desc2, W1, g_HT, sm.g);
    gsync(1 * NBLK);
    attn_phase<false>(bid, g_HT, as1, ad1, b1, g_XT, sm.a);
    gsync(2 * NBLK);
    gemm_phase<1>(bid, g_XT, nullptr, nullptr, W1, g_HT, sm.g);
    gsync(3 * NBLK);
    attn_phase<true>(bid, g_HT, as1, ad1, b1, g_XT, sm.a);
    gsync(4 * NBLK);
    gemm_phase<1>(bid, g_XT, nullptr, nullptr, W1, g_HT, sm.g);
    gsync(5 * NBLK);
    attn_phase<false>(bid, g_HT, as1, ad1, b1, g_XT, sm.a);
    gsync(6 * NBLK);
    gemm_phase<1>(bid, g_XT, nullptr, nullptr, W1, g_HT, sm.g);
    gsync(7 * NBLK);
    attn_phase<true>(bid, g_HT, as1, ad1, b1, g_XT, sm.a);
    gsync(8 * NBLK);
    gemm_phase<2>(bid, g_XT, nullptr, nullptr, W2, g_H, sm.g);
    gsync(9 * NBLK);
    dots_phase(bid, g_H, as2, ad2, g_asf, g_adf);
    gsync(10 * NBLK);
    if (bid < 128) final_phase(bid, g_H, g_asf, g_adf, b2, out, sm.f);
}

// ---------------------------------------------------------------------------
extern "C" void kernel_launch(void* const* d_in, const int* in_sizes, int n_in,
                              void* d_out, int out_size) {
    const float* desc1 = (const float*)d_in[0];
    const float* desc2 = (const float*)d_in[1];
    const float* W1 = (const float*)d_in[2];
    const float* as1 = (const float*)d_in[3];
    const float* ad1 = (const float*)d_in[4];
    const float* b1 = (const float*)d_in[5];
    const float* W2 = (const float*)d_in[6];
    const float* as2 = (const float*)d_in[7];
    const float* ad2 = (const float*)d_in[8];
    const float* b2 = (const float*)d_in[9];
    float* out = (float*)d_out;

    reset_bar<<<1, 1>>>();
    mega<<<NBLK, NTHR>>>(desc1, desc2, W1, as1, ad1, b1, W2, as2, ad2, b2, out);
}

// round 9
// speedup vs baseline: 1.3539x; 1.3539x over previous
#include <cuda_runtime.h>
#include <math.h>

#define NSLOPE 0.2f
#define NN 1024
#define F 128

__device__ float g_XT[NN * F];   // feature-major activations [f][n]
__device__ float g_HT[NN * F];   // feature-major conv features [f][n]
__device__ float g_H[NN * F];    // row-major (final conv only)
__device__ float g_asf[NN];
__device__ float g_adf[NN];

__device__ __forceinline__ float lrelu(float x) { return x > 0.f ? x : NSLOPE * x; }

// order-preserving float->uint encode
__device__ __forceinline__ unsigned fenc(float f) {
    unsigned u = __float_as_uint(f);
    return (u & 0x80000000u) ? ~u : (u | 0x80000000u);
}

// ---------------------------------------------------------------------------
// GEMM. grid 256: (row-block 0..127) x (col-half 0..1); block 128 threads.
// 8 rows x 64 cols per block, 4 rows/thread. W transposed in smem (pad 129).
// MODE 0: read desc1|desc2 rows, write HT.  MODE 1: read XT, write HT.
// MODE 2: read XT, write H (row-major).
template <int MODE>
__global__ void gemmT(const float* __restrict__ XT, const float* __restrict__ d1,
                      const float* __restrict__ d2, const float* __restrict__ W,
                      float* __restrict__ OUT) {
    __shared__ float Wt[64 * 129];
    __shared__ __align__(16) float xs[8][128];
    int tid = threadIdx.x;
    int bx = blockIdx.x;
    int cs = (bx & 1) * 64;
    int n0 = (bx >> 1) * 8;
    int c = tid & 63;
    int rh = tid >> 6;

    // W[k][cs..cs+63] transposed into Wt[c][k]
#pragma unroll
    for (int i = 0; i < 16; i++) {
        int f = tid + i * 128;
        int k = f >> 4, cq = f & 15;
        float4 w4 = *reinterpret_cast<const float4*>(W + k * F + cs + cq * 4);
        Wt[(cq * 4 + 0) * 129 + k] = w4.x;
        Wt[(cq * 4 + 1) * 129 + k] = w4.y;
        Wt[(cq * 4 + 2) * 129 + k] = w4.z;
        Wt[(cq * 4 + 3) * 129 + k] = w4.w;
    }
    // 8 rows of input into xs[r][k]
    if (MODE == 0) {
#pragma unroll
        for (int i = 0; i < 2; i++) {
            int f = tid + i * 128;
            int r = f >> 5, cq = f & 31;
            int n = n0 + r;
            float4 x4 = (n < 512) ? reinterpret_cast<const float4*>(d1)[n * 32 + cq]
                                  : reinterpret_cast<const float4*>(d2)[(n - 512) * 32 + cq];
            *reinterpret_cast<float4*>(&xs[r][cq * 4]) = x4;
        }
    } else {
        const float4* XT4 = reinterpret_cast<const float4*>(XT);
#pragma unroll
        for (int i = 0; i < 2; i++) {
            int u = tid + i * 128;          // 0..255
            int k = u >> 1, q = u & 1;      // feature k, node-quad q
            float4 x4 = XT4[k * 256 + (n0 >> 2) + q];
            xs[q * 4 + 0][k] = x4.x;
            xs[q * 4 + 1][k] = x4.y;
            xs[q * 4 + 2][k] = x4.z;
            xs[q * 4 + 3][k] = x4.w;
        }
    }
    __syncthreads();

    float acc[4] = {0, 0, 0, 0};
#pragma unroll 4
    for (int kq = 0; kq < 32; kq++) {
        float w0 = Wt[c * 129 + kq * 4 + 0];
        float w1 = Wt[c * 129 + kq * 4 + 1];
        float w2 = Wt[c * 129 + kq * 4 + 2];
        float w3 = Wt[c * 129 + kq * 4 + 3];
#pragma unroll
        for (int r = 0; r < 4; r++) {
            float4 x = *reinterpret_cast<const float4*>(&xs[rh * 4 + r][kq * 4]);
            acc[r] = fmaf(x.x, w0, fmaf(x.y, w1, fmaf(x.z, w2, fmaf(x.w, w3, acc[r]))));
        }
    }
    if (MODE == 2) {
#pragma unroll
        for (int r = 0; r < 4; r++) OUT[(n0 + rh * 4 + r) * F + cs + c] = acc[r];
    } else {
        float* p = OUT + (cs + c) * NN + n0 + rh * 4;
        *reinterpret_cast<float4*>(p) = make_float4(acc[0], acc[1], acc[2], acc[3]);
    }
}

// ---------------------------------------------------------------------------
__device__ __forceinline__ float2 warp_incl_scan2(float2 v, int lane) {
#pragma unroll
    for (int d = 1; d < 32; d <<= 1) {
        float x = __shfl_up_sync(0xffffffffu, v.x, d);
        float y = __shfl_up_sync(0xffffffffu, v.y, d);
        if (lane >= d) { v.x += x; v.y += y; }
    }
    return v;
}
__device__ __forceinline__ float2 warp_incl_sufscan2(float2 v, int lane) {
#pragma unroll
    for (int d = 1; d < 32; d <<= 1) {
        float x = __shfl_down_sync(0xffffffffu, v.x, d);
        float y = __shfl_down_sync(0xffffffffu, v.y, d);
        if (lane + d < 32) { v.x += x; v.y += y; }
    }
    return v;
}

// ---------------------------------------------------------------------------
// GAT attention (128 heads, C=1), 1 head/block, grid (128, 2), 512 threads,
// 1 element/thread (4096 warps chip-wide). Packed-key bitonic sort
// (order-preserving encode | 9-bit src index) -> one u32 min/max per
// exchange; exact keys/values regathered by index for the branch-sum scans.
template <bool CROSS>
__global__ void attnT(const float* __restrict__ HT, const float* __restrict__ a_src,
                      const float* __restrict__ a_dst, const float* __restrict__ bias,
                      float* __restrict__ XTo) {
    __shared__ unsigned sU[512];
    __shared__ float sK0[512];
    __shared__ float sV0[512];
    __shared__ __align__(16) float4 sSP[513];  // (suf1, suf1v, pre2, pre2v)
    __shared__ float2 wt1[16], wt2[16];

    int t = threadIdx.x;        // 0..511 = element index
    int lane = t & 31;
    int w = t >> 5;             // warp 0..15
    int h = blockIdx.x;
    int dg = blockIdx.y;
    int sg = CROSS ? (1 - dg) : dg;

    float asrc = a_src[h], adst = a_dst[h], bh = bias[h];

    float sv = HT[h * NN + sg * 512 + t];
    float hd = HT[h * NN + dg * 512 + t];
    float kk = sv * asrc;
    sK0[t] = kk;
    sV0[t] = sv;
    unsigned u = (fenc(kk) & ~511u) | (unsigned)t;
    __syncthreads();

    // bitonic sort ascending on packed keys
    for (int K2 = 2; K2 <= 512; K2 <<= 1) {
        for (int J = K2 >> 1; J; J >>= 1) {
            bool keepSmall = (((t & K2) == 0) == ((t & J) == 0));
            unsigned uo;
            if (J >= 32) {
                __syncthreads();
                sU[t] = u;
                __syncthreads();
                uo = sU[t ^ J];
            } else {
                uo = __shfl_xor_sync(0xffffffffu, u, J);
            }
            u = keepSmall ? umin(u, uo) : umax(u, uo);
        }
    }

    __syncthreads();
    sU[t] = u;
    __syncthreads();
    float M = sK0[sU[511] & 511u];

    // regather exact key/value of this thread's sorted element
    unsigned idx = u & 511u;
    float kx = sK0[idx];
    float vx = sV0[idx];

    float q1 = __expf(kx - M);
    float q2 = __expf(NSLOPE * (kx - M));
    float2 p1 = make_float2(q1, q1 * vx);
    float2 p2 = make_float2(q2, q2 * vx);

    // block scans in sorted order (element order == t)
    float2 tincl = warp_incl_scan2(p2, lane);   // inclusive prefix of p2
    float2 texcl;
    texcl.x = __shfl_up_sync(0xffffffffu, tincl.x, 1);
    texcl.y = __shfl_up_sync(0xffffffffu, tincl.y, 1);
    if (lane == 0) texcl = make_float2(0.f, 0.f);
    if (lane == 31) wt2[w] = tincl;

    float2 sincl = warp_incl_sufscan2(p1, lane);  // inclusive suffix of p1
    if (lane == 0) wt1[w] = sincl;
    __syncthreads();

    float2 base2 = texcl, base1 = make_float2(0.f, 0.f);
#pragma unroll
    for (int ww = 0; ww < 16; ww++) {
        if (ww < w) { base2.x += wt2[ww].x; base2.y += wt2[ww].y; }
        if (ww > w) { base1.x += wt1[ww].x; base1.y += wt1[ww].y; }
    }
    sSP[t] = make_float4(base1.x + sincl.x, base1.y + sincl.y, base2.x, base2.y);
    // total prefix = warp offsets + OWN inclusive prefix (base2 already holds
    // texcl, so add only the own element p2 — NOT tincl, which double-counts)
    if (t == 511)
        sSP[512] = make_float4(0.f, 0.f, base2.x + p2.x, base2.y + p2.y);
    __syncthreads();

    // per-dst: binary search rank of threshold -ad (encoded domain)
    float adv = hd * adst;
    unsigned ue = fenc(-adv);
    int pos = 0;
#pragma unroll
    for (int half = 256; half >= 1; half >>= 1)
        if (sU[pos + half - 1] <= ue) pos += half;
    if (sU[pos] <= ue) pos++;

    float4 Sv = sSP[pos];
    float T = M + adv;
    float tmax = T, ts = 0.f;
    if (CROSS) {
        ts = hd * asrc + adv;  // self-loop score
        tmax = fmaxf(tmax, ts);
    }
    float C = lrelu(tmax);
    float f1 = __expf(T - C);
    float f2 = __expf(NSLOPE * T - C);
    float num = f1 * Sv.y + f2 * Sv.w;
    float den = f1 * Sv.x + f2 * Sv.z;
    if (CROSS) {
        float ws = __expf(lrelu(ts) - C);
        num = fmaf(ws, hd, num);
        den += ws;
    }
    float o = num / (den + 1e-16f) + bh;
    o = o > 0.f ? o : expm1f(o);  // ELU
    XTo[h * NN + dg * 512 + t] = o;
}

// ---------------------------------------------------------------------------
__global__ void dots_kernel(const float* __restrict__ H, const float* __restrict__ a_s,
                            const float* __restrict__ a_d, float* __restrict__ asf,
                            float* __restrict__ adf) {
    int n = blockIdx.x * 8 + (threadIdx.x >> 5);
    int lane = threadIdx.x & 31;
    float4 hv = reinterpret_cast<const float4*>(H + n * F)[lane];
    float4 s4 = reinterpret_cast<const float4*>(a_s)[lane];
    float4 d4 = reinterpret_cast<const float4*>(a_d)[lane];
    float s1 = hv.x * s4.x + hv.y * s4.y + hv.z * s4.z + hv.w * s4.w;
    float s2 = hv.x * d4.x + hv.y * d4.y + hv.z * d4.z + hv.w * d4.w;
#pragma unroll
    for (int o = 16; o; o >>= 1) {
        s1 += __shfl_xor_sync(0xffffffffu, s1, o);
        s2 += __shfl_xor_sync(0xffffffffu, s2, o);
    }
    if (lane == 0) { asf[n] = s1; adf[n] = s2; }
}

// final cross-attention: 8 dsts/block, 256 threads (128 cols x 2 s-halves)
__global__ void final_attn(const float* __restrict__ H, const float* __restrict__ asf,
                           const float* __restrict__ adf, const float* __restrict__ bias,
                           float* __restrict__ out) {
    int d0 = blockIdx.x * 8;
    int dg = d0 >> 9;
    int sg = 1 - dg;
    int tid = threadIdx.x;
    int col = tid & 127, sh = tid >> 7;
    int w = tid >> 5, lane = tid & 31;

    __shared__ float sAsf[512];
    __shared__ float4 swq[512][2];
    __shared__ float sAdf[8], sM[8], sSelf[8], sDen[8];
    __shared__ float pr[8][128];
    __shared__ float dred[8][256];
    __shared__ float red[8];

    float mloc = -1e30f;
    for (int s = tid; s < 512; s += 256) {
        float v = asf[sg * 512 + s];
        sAsf[s] = v;
        mloc = fmaxf(mloc, v);
    }
#pragma unroll
    for (int o = 16; o; o >>= 1) mloc = fmaxf(mloc, __shfl_xor_sync(0xffffffffu, mloc, o));
    if (lane == 0) red[w] = mloc;
    __syncthreads();
    float maxasf = red[0];
#pragma unroll
    for (int ww = 1; ww < 8; ww++) maxasf = fmaxf(maxasf, red[ww]);

    if (tid < 8) {
        int dn = d0 + tid;
        float ad = adf[dn];
        float ts = asf[dn] + ad;
        float tmax = fmaxf(maxasf + ad, ts);
        float mm = lrelu(tmax);
        sAdf[tid] = ad;
        sM[tid] = mm;
        sSelf[tid] = __expf(lrelu(ts) - mm);
    }
    __syncthreads();

    float dl[8] = {0, 0, 0, 0, 0, 0, 0, 0};
    for (int s = tid; s < 512; s += 256) {
        float a = sAsf[s];
        float wv[8];
#pragma unroll
        for (int d = 0; d < 8; d++) {
            wv[d] = __expf(lrelu(a + sAdf[d]) - sM[d]);
            dl[d] += wv[d];
        }
        swq[s][0] = make_float4(wv[0], wv[1], wv[2], wv[3]);
        swq[s][1] = make_float4(wv[4], wv[5], wv[6], wv[7]);
    }
#pragma unroll
    for (int d = 0; d < 8; d++) dred[d][tid] = dl[d];
    __syncthreads();
    {
        float x = dred[w][lane] + dred[w][lane + 32] + dred[w][lane + 64] + dred[w][lane + 96] +
                  dred[w][lane + 128] + dred[w][lane + 160] + dred[w][lane + 192] + dred[w][lane + 224];
#pragma unroll
        for (int o = 16; o; o >>= 1) x += __shfl_xor_sync(0xffffffffu, x, o);
        if (lane == 0) sDen[w] = x;
    }
    __syncthreads();

    float acc[8] = {0, 0, 0, 0, 0, 0, 0, 0};
    const float* Hs = H + (sg * 512 + sh * 256) * F + col;
#pragma unroll 2
    for (int s = 0; s < 256; s++) {
        float hv = Hs[s * F];
        int ss = sh * 256 + s;
        float4 w0 = swq[ss][0];
        float4 w1 = swq[ss][1];
        acc[0] = fmaf(w0.x, hv, acc[0]);
        acc[1] = fmaf(w0.y, hv, acc[1]);
        acc[2] = fmaf(w0.z, hv, acc[2]);
        acc[3] = fmaf(w0.w, hv, acc[3]);
        acc[4] = fmaf(w1.x, hv, acc[4]);
        acc[5] = fmaf(w1.y, hv, acc[5]);
        acc[6] = fmaf(w1.z, hv, acc[6]);
        acc[7] = fmaf(w1.w, hv, acc[7]);
    }
    if (sh) {
#pragma unroll
        for (int d = 0; d < 8; d++) pr[d][col] = acc[d];
    }
    __syncthreads();
    if (!sh) {
        float bc = bias[col];
#pragma unroll
        for (int d = 0; d < 8; d++) {
            int dn = d0 + d;
            float Hdv = H[dn * F + col];
            float num = acc[d] + pr[d][col] + sSelf[d] * Hdv;
            out[dn * F + col] = num / (sDen[d] + sSelf[d] + 1e-16f) + bc;
        }
    }
}

// ---------------------------------------------------------------------------
extern "C" void kernel_launch(void* const* d_in, const int* in_sizes, int n_in,
                              void* d_out, int out_size) {
    const float* desc1 = (const float*)d_in[0];
    const float* desc2 = (const float*)d_in[1];
    const float* W1 = (const float*)d_in[2];
    const float* as1 = (const float*)d_in[3];
    const float* ad1 = (const float*)d_in[4];
    const float* b1 = (const float*)d_in[5];
    const float* W2 = (const float*)d_in[6];
    const float* as2 = (const float*)d_in[7];
    const float* ad2 = (const float*)d_in[8];
    const float* b2 = (const float*)d_in[9];
    float* out = (float*)d_out;

    float *XT, *HT, *H, *asf, *adf;
    cudaGetSymbolAddress((void**)&XT, g_XT);
    cudaGetSymbolAddress((void**)&HT, g_HT);
    cudaGetSymbolAddress((void**)&H, g_H);
    cudaGetSymbolAddress((void**)&asf, g_asf);
    cudaGetSymbolAddress((void**)&adf, g_adf);

    dim3 ag(128, 2);
    // conv1: inside (concat fused into gemm)
    gemmT<0><<<256, 128>>>(nullptr, desc1, desc2, W1, HT);
    attnT<false><<<ag, 512>>>(HT, as1, ad1, b1, XT);
    // conv2: cross
    gemmT<1><<<256, 128>>>(XT, nullptr, nullptr, W1, HT);
    attnT<true><<<ag, 512>>>(HT, as1, ad1, b1, XT);
    // conv3: inside
    gemmT<1><<<256, 128>>>(XT, nullptr, nullptr, W1, HT);
    attnT<false><<<ag, 512>>>(HT, as1, ad1, b1, XT);
    // conv4: cross
    gemmT<1><<<256, 128>>>(XT, nullptr, nullptr, W1, HT);
    attnT<true><<<ag, 512>>>(HT, as1, ad1, b1, XT);
    // final conv: cross, heads=1, out_ch=128, no ELU (row-major H)
    gemmT<2><<<256, 128>>>(XT, nullptr, nullptr, W2, H);
    dots_kernel<<<128, 256>>>(H, as2, ad2, asf, adf);
    final_attn<<<128, 256>>>(H, asf, adf, b2, out);
}